// round 8
// baseline (speedup 1.0000x reference)
#include <cuda_runtime.h>
#include <cuda_fp16.h>
#include <cstdint>

// ---------------------------------------------------------------------------
// EvalNet: EmbeddingBag(sum,pad) -> screlu -> fc2(1024->32) -> screlu
//          -> bucketed cp/wdl heads.   (sm_100 SIMT; no tcgen05)
// P : emb fp32->fp16; build duplicated-pair weights g_wdup[c][j]=(w,w).
// K1: 128-col chunked SMEM gather over fp16 table; depth-2 HADD2 tree +
//     f32x2 accumulation; h written PAIR-INTERLEAVED fp32.
// K2: cp.async double-buffered (h + wdup) fc2; 2 pairs x 4 j FFMA2 tiles;
//     bucketed heads.
// ---------------------------------------------------------------------------

#define HIDDEN   1024
#define NROWS    769
#define MAX_B    16384
#define TILE     32

#define CHUNK1   128
#define NCHUNKS1 (HIDDEN / CHUNK1)   // 8
#define NGROUPS1 18                  // 8*18 = 144 blocks
#define K1T      512

#define K2T      128
#define TS2      64                  // samples per K2 block
#define CHUNK2   64
#define NCH2     (HIDDEN / CHUNK2)   // 16
#define HSTRIDE  66                  // h row stride in ull (528 B, 16-aligned)

__device__ float  g_h[(size_t)MAX_B * HIDDEN];   // pair-interleaved hidden
__device__ __half g_emb_h[NROWS * HIDDEN];       // fp16 table
__device__ float4 g_wdup[HIDDEN * 8];            // [c][j] (w,w) pairs

__device__ __forceinline__ float screlu1(float v)
{
    float c = fminf(fmaxf(v, 0.0f), 1.0f);
    return c * c;
}

__device__ __forceinline__ void fma2(unsigned long long& acc,
                                     unsigned long long a,
                                     unsigned long long b)
{
    asm("fma.rn.f32x2 %0, %1, %2, %0;" : "+l"(acc) : "l"(a), "l"(b));
}

__device__ __forceinline__ void add2(unsigned long long& acc,
                                     unsigned long long v)
{
    asm("add.rn.f32x2 %0, %0, %1;" : "+l"(acc) : "l"(v));
}

__device__ __forceinline__ uint32_t smem_u32(const void* p)
{
    uint32_t a;
    asm("{ .reg .u64 t; cvta.to.shared.u64 t, %1; cvt.u32.u64 %0, t; }"
        : "=r"(a) : "l"(p));
    return a;
}

__device__ __forceinline__ void cp_async16(uint32_t dst, const void* src)
{
    asm volatile("cp.async.ca.shared.global [%0], [%1], 16;"
                 :: "r"(dst), "l"(__cvta_generic_to_global(src)));
}

#define CP_COMMIT() asm volatile("cp.async.commit_group;" ::: "memory")
#define CP_WAIT0()  asm volatile("cp.async.wait_group 0;" ::: "memory")

union F2U { float2 f; unsigned long long u; };

#define H2(u) (*(const __half2*)&(u))

// ---------------------------------------------------------------------------
// P: prep — emb fp16 (blocks 0..768), g_wdup build (block 769).
// ---------------------------------------------------------------------------
__global__ __launch_bounds__(512)
void prep_kernel(const float* __restrict__ emb,
                 const float* __restrict__ fc2_w)
{
    const int b = blockIdx.x, tid = threadIdx.x;
    if (b < NROWS) {
        const float2* src = (const float2*)(emb + b * HIDDEN);
        __half2* dst = (__half2*)(g_emb_h + b * HIDDEN);
        dst[tid] = __floats2half2_rn(src[tid].x, src[tid].y);
    } else {
        // wdup[c*32 + j] = (w[j][c], w[j][c]); coalesced reads of fc2_w
        float2* wd = (float2*)g_wdup;
        #pragma unroll
        for (int r = 0; r < 64; r++) {
            int i = tid + r * 512;          // i = j*1024 + c
            int j = i >> 10, c = i & 1023;
            float w = fc2_w[i];
            wd[c * 32 + j] = make_float2(w, w);
        }
    }
}

// ---------------------------------------------------------------------------
// K1: gather + bias + screlu over a 128-col fp16 table slice.
// Depth-2 HADD2 tree: 4 rows summed in fp16, then f32x2 accumulate.
// ---------------------------------------------------------------------------
__global__ __launch_bounds__(K1T)
void gather_kernel(const void* __restrict__ xv,
                   const float* __restrict__ bias1,
                   int B)
{
    extern __shared__ char smem[];
    __half* s_tab  = (__half*)smem;                                  // NROWS*CHUNK1*2
    int*    s_idx  = (int*)(smem + NROWS * CHUNK1 * 2);              // 2*1024*4
    float*  s_bias = (float*)(smem + NROWS * CHUNK1 * 2 + 8192);     // CHUNK1*4
    int*    s_nz   = (int*)(smem + NROWS * CHUNK1 * 2 + 8192 + CHUNK1 * 4);

    const int tid   = threadIdx.x;
    const int cbase = blockIdx.x * CHUNK1;

    if (tid == 0) *s_nz = 0;
    __syncthreads();

    if (tid < 64) {
        if (((const unsigned int*)xv)[2 * tid + 1]) atomicOr(s_nz, 1);
    }

    {
        const uint4* src = (const uint4*)g_emb_h;       // row stride 128 uint4
        uint4*       dst = (uint4*)s_tab;               // row stride 16 uint4
        const int cb8 = cbase >> 3;
        for (int i = tid; i < NROWS * 16; i += K1T) {
            int row = i >> 4, u = i & 15;
            dst[i] = src[row * 128 + cb8 + u];
        }
    }
    if (tid < CHUNK1) s_bias[tid] = bias1[cbase + tid];
    __syncthreads();

    const int is64 = (*s_nz == 0);

    const int s   = tid >> 4;
    const int q   = tid & 15;
    const int odd = s & 1;

    const int spg     = (((B + NGROUPS1 - 1) / NGROUPS1) + TILE - 1) & ~(TILE - 1);
    const int s_begin = blockIdx.y * spg;
    const int s_end   = min(B, s_begin + spg);

    const int*       x32 = (const int*)xv;
    const long long* x64 = (const long long*)xv;
    float2*          ghp = (float2*)g_h;
    const uint4*     tab4 = (const uint4*)s_tab;

    int pre0 = NROWS - 1, pre1 = NROWS - 1;
    if (s_begin < s_end) {
        #pragma unroll
        for (int k = 0; k < 2; k++) {
            int j = tid + k * K1T;
            int samp = s_begin + (j >> 5);
            int v = NROWS - 1;
            if (samp < B) {
                int r = j & 31;
                v = is64 ? (int)x64[(size_t)samp * 32 + r]
                         : x32[samp * 32 + r];
            }
            if (k == 0) pre0 = v; else pre1 = v;
        }
    }

    int buf = 0;
    for (int t0 = s_begin; t0 < s_end; t0 += TILE) {
        s_idx[buf * 1024 + tid]       = pre0;
        s_idx[buf * 1024 + tid + K1T] = pre1;
        __syncthreads();

        int tn = t0 + TILE;
        if (tn < s_end) {
            #pragma unroll
            for (int k = 0; k < 2; k++) {
                int j = tid + k * K1T;
                int samp = tn + (j >> 5);
                int v = NROWS - 1;
                if (samp < B) {
                    int r = j & 31;
                    v = is64 ? (int)x64[(size_t)samp * 32 + r]
                             : x32[samp * 32 + r];
                }
                if (k == 0) pre0 = v; else pre1 = v;
            }
        }

        const int* idx = &s_idx[buf * 1024 + s * 32];

        unsigned long long a0 = 0ull, a1 = 0ull, a2 = 0ull, a3 = 0ull;
        #pragma unroll
        for (int r0 = 0; r0 < 32; r0 += 8) {
            int id[8];
            #pragma unroll
            for (int k = 0; k < 8; k++) id[k] = idx[r0 + k];
            uint4 v[8];
            #pragma unroll
            for (int k = 0; k < 8; k++) v[k] = tab4[id[k] * 16 + q];

            // depth-2 fp16 tree per component, then f32x2 accumulate
            #define TREE(COMP, ACC) do {                                         \
                __half2 l0 = __hadd2(__hadd2(H2(v[0].COMP), H2(v[1].COMP)),      \
                                     __hadd2(H2(v[2].COMP), H2(v[3].COMP)));     \
                __half2 l1 = __hadd2(__hadd2(H2(v[4].COMP), H2(v[5].COMP)),      \
                                     __hadd2(H2(v[6].COMP), H2(v[7].COMP)));     \
                F2U t0_, t1_;                                                    \
                t0_.f = __half22float2(l0);                                      \
                t1_.f = __half22float2(l1);                                      \
                add2(ACC, t0_.u);                                                \
                add2(ACC, t1_.u);                                                \
            } while (0)

            TREE(x, a0);
            TREE(y, a1);
            TREE(z, a2);
            TREE(w, a3);
            #undef TREE
        }

        int samp = t0 + s;

        float h[8];
        {
            F2U u0, u1, u2, u3;
            u0.u = a0; u1.u = a1; u2.u = a2; u3.u = a3;
            h[0] = u0.f.x; h[1] = u0.f.y; h[2] = u1.f.x; h[3] = u1.f.y;
            h[4] = u2.f.x; h[5] = u2.f.y; h[6] = u3.f.x; h[7] = u3.f.y;
            const float4 b0 = ((const float4*)s_bias)[2 * q];
            const float4 b1 = ((const float4*)s_bias)[2 * q + 1];
            h[0] = screlu1(h[0] + b0.x); h[1] = screlu1(h[1] + b0.y);
            h[2] = screlu1(h[2] + b0.z); h[3] = screlu1(h[3] + b0.w);
            h[4] = screlu1(h[4] + b1.x); h[5] = screlu1(h[5] + b1.y);
            h[6] = screlu1(h[6] + b1.z); h[7] = screlu1(h[7] + b1.w);
        }

        float p[8];
        #pragma unroll
        for (int k = 0; k < 8; k++)
            p[k] = __shfl_xor_sync(0xffffffffu, h[k], 16);

        if (samp < B) {
            size_t pr = (size_t)(samp >> 1);
            float2* base = ghp + pr * HIDDEN + cbase + 8 * q + odd * 4;
            if (!odd) {
                ((float4*)base)[0] = make_float4(h[0], p[0], h[1], p[1]);
                ((float4*)base)[1] = make_float4(h[2], p[2], h[3], p[3]);
            } else {
                ((float4*)base)[0] = make_float4(p[4], h[4], p[5], h[5]);
                ((float4*)base)[1] = make_float4(p[6], h[6], p[7], h[7]);
            }
        }
        buf ^= 1;
    }
}

// ---------------------------------------------------------------------------
// K2: fc2 via 2-pair x 4-j FFMA2 tiles; cp.async double-buffered h + wdup.
// 128 threads, 64 samples/block. pg = tid>>3 owns pairs {2pg, 2pg+1};
// jq = tid&7 owns j {4jq..4jq+3}.
// ---------------------------------------------------------------------------
#define K2_OFF_H    0
#define K2_HBUF     16896              // 32 pairs * 66 ull * 8
#define K2_OFF_W    33792
#define K2_WBUF     16384              // 64 c * 32 j * 8 (dup pairs)
#define K2_OFF_CPW  66560
#define K2_OFF_WDLW 67584
#define K2_OFF_FB   70656
#define K2_OFF_CB   70784
#define K2_OFF_WB   70816
#define K2_OFF_NZ   70912
#define K2_SMEM     70928

__global__ __launch_bounds__(K2T)
void fc_kernel(const void* __restrict__ xv,
               const float* __restrict__ fc2_b,
               const float* __restrict__ cp_w,  const float* __restrict__ cp_b,
               const float* __restrict__ wdl_w, const float* __restrict__ wdl_b,
               const void* __restrict__ pcv, float* __restrict__ out, int B)
{
    extern __shared__ char smem[];
    const uint32_t sbase = smem_u32(smem);

    float* s_cp_w  = (float*)(smem + K2_OFF_CPW);
    float* s_wdl_w = (float*)(smem + K2_OFF_WDLW);
    float* s_fc2_b = (float*)(smem + K2_OFF_FB);
    float* s_cp_b  = (float*)(smem + K2_OFF_CB);
    float* s_wdl_b = (float*)(smem + K2_OFF_WB);
    int*   s_nz    = (int*)(smem + K2_OFF_NZ);

    const int tid = threadIdx.x;
    const int s0  = blockIdx.x * TS2;
    const int p0  = s0 >> 1;

    if (tid == 0) *s_nz = 0;
    __syncthreads();
    if (tid < 64) {
        if (((const unsigned int*)xv)[2 * tid + 1]) atomicOr(s_nz, 1);
    }
    for (int i = tid; i < 8 * 32; i += K2T)  s_cp_w[i]  = cp_w[i];
    for (int i = tid; i < 24 * 32; i += K2T) s_wdl_w[i] = wdl_w[i];
    if (tid < 32) s_fc2_b[tid] = fc2_b[tid];
    if (tid < 8)  s_cp_b[tid]  = cp_b[tid];
    if (tid < 24) s_wdl_b[tid] = wdl_b[tid];

    const float2* ghp = (const float2*)g_h;

    auto stage = [&](int k) {
        int buf = k & 1;
        int c0  = k * CHUNK2;
        uint32_t hdst = sbase + K2_OFF_H + buf * K2_HBUF;
        uint32_t wdst = sbase + K2_OFF_W + buf * K2_WBUF;
        // h: 32 pair-rows x 64 c (fp32 pairs) = 1024 cp16
        #pragma unroll
        for (int r = 0; r < 8; r++) {
            int u   = tid + r * K2T;
            int p   = u >> 5;            // pair row 0..31
            int c16 = u & 31;            // 16B unit within row
            cp_async16(hdst + (uint32_t)(p * (HSTRIDE * 8) + c16 * 16),
                       ghp + ((size_t)(p0 + p) * HIDDEN + c0 + c16 * 2));
        }
        // wdup: contiguous 16KB block for this chunk
        const char* wsrc = (const char*)g_wdup + (size_t)k * K2_WBUF;
        #pragma unroll
        for (int r = 0; r < 8; r++) {
            int u = tid + r * K2T;
            cp_async16(wdst + (uint32_t)(u * 16), wsrc + u * 16);
        }
        CP_COMMIT();
    };

    stage(0);

    const int jq = tid & 7;      // j = 4jq .. 4jq+3
    const int pg = tid >> 3;     // pairs 2pg, 2pg+1

    unsigned long long acc[2][4];
    #pragma unroll
    for (int p = 0; p < 2; p++)
        #pragma unroll
        for (int j = 0; j < 4; j++) acc[p][j] = 0ull;

    for (int k = 0; k < NCH2; k++) {
        CP_WAIT0();
        __syncthreads();
        if (k + 1 < NCH2) stage(k + 1);   // overlaps compute below

        int buf = k & 1;
        const unsigned long long* hb =
            (const unsigned long long*)(smem + K2_OFF_H + buf * K2_HBUF);
        const ulonglong2* wb =
            (const ulonglong2*)(smem + K2_OFF_W + buf * K2_WBUF);
        const unsigned long long* h0 = hb + (2 * pg) * HSTRIDE;
        const unsigned long long* h1 = hb + (2 * pg + 1) * HSTRIDE;

        #pragma unroll 4
        for (int c = 0; c < CHUNK2; c++) {
            unsigned long long hv0 = h0[c];
            unsigned long long hv1 = h1[c];
            const ulonglong2* wp = wb + c * 16 + jq * 2;
            ulonglong2 w01 = wp[0];
            ulonglong2 w23 = wp[1];
            fma2(acc[0][0], hv0, w01.x);
            fma2(acc[0][1], hv0, w01.y);
            fma2(acc[0][2], hv0, w23.x);
            fma2(acc[0][3], hv0, w23.y);
            fma2(acc[1][0], hv1, w01.x);
            fma2(acc[1][1], hv1, w01.y);
            fma2(acc[1][2], hv1, w23.x);
            fma2(acc[1][3], hv1, w23.y);
        }
        __syncthreads();
    }

    // h2 = screlu(acc + b) into smem (reuse hbuf: 64*33*4 = 8448 B)
    float* s_h2 = (float*)(smem + K2_OFF_H);
    #pragma unroll
    for (int p = 0; p < 2; p++) {
        #pragma unroll
        for (int jj = 0; jj < 4; jj++) {
            int j = 4 * jq + jj;
            F2U u; u.u = acc[p][jj];
            s_h2[(4 * pg + 2 * p)     * 33 + j] = screlu1(u.f.x + s_fc2_b[j]);
            s_h2[(4 * pg + 2 * p + 1) * 33 + j] = screlu1(u.f.y + s_fc2_b[j]);
        }
    }
    __syncthreads();

    // heads: one thread per sample
    if (tid < TS2) {
        int samp = s0 + tid;
        if (samp < B) {
            const int is64 = (*s_nz == 0);
            int pc = is64 ? (int)((const long long*)pcv)[samp]
                          : ((const int*)pcv)[samp];
            int bkt = (pc - 2) * 8 / 30;
            bkt = max(0, min(7, bkt));

            const float* h2 = &s_h2[tid * 33];
            float cp = s_cp_b[bkt];
            float w0 = s_wdl_b[bkt * 3 + 0];
            float w1 = s_wdl_b[bkt * 3 + 1];
            float w2 = s_wdl_b[bkt * 3 + 2];
            const float* cw  = &s_cp_w[bkt * 32];
            const float* ww0 = &s_wdl_w[(bkt * 3 + 0) * 32];
            const float* ww1 = &s_wdl_w[(bkt * 3 + 1) * 32];
            const float* ww2 = &s_wdl_w[(bkt * 3 + 2) * 32];
            #pragma unroll
            for (int j = 0; j < 32; j++) {
                float hh = h2[j];
                cp = fmaf(hh, cw[j],  cp);
                w0 = fmaf(hh, ww0[j], w0);
                w1 = fmaf(hh, ww1[j], w1);
                w2 = fmaf(hh, ww2[j], w2);
            }
            out[samp] = cp;
            out[B + samp * 3 + 0] = w0;
            out[B + samp * 3 + 1] = w1;
            out[B + samp * 3 + 2] = w2;
        }
    }
}

// ---------------------------------------------------------------------------
extern "C" void kernel_launch(void* const* d_in, const int* in_sizes, int n_in,
                              void* d_out, int out_size)
{
    const void*  x      = d_in[0];
    const void*  pc     = d_in[1];
    const float* emb    = (const float*)d_in[2];
    const float* bias1  = (const float*)d_in[3];
    const float* fc2_w  = (const float*)d_in[4];
    const float* fc2_b  = (const float*)d_in[5];
    const float* cp_w   = (const float*)d_in[6];
    const float* cp_b   = (const float*)d_in[7];
    const float* wdl_w  = (const float*)d_in[8];
    const float* wdl_b  = (const float*)d_in[9];

    int B = in_sizes[0] / 32;
    if (B > MAX_B) B = MAX_B;

    prep_kernel<<<NROWS + 1, 512>>>(emb, fc2_w);

    const int k1_smem = NROWS * CHUNK1 * 2 + 8192 + CHUNK1 * 4 + 16;
    cudaFuncSetAttribute(gather_kernel,
                         cudaFuncAttributeMaxDynamicSharedMemorySize, k1_smem);
    dim3 g1(NCHUNKS1, NGROUPS1);
    gather_kernel<<<g1, K1T, k1_smem>>>(x, bias1, B);

    cudaFuncSetAttribute(fc_kernel,
                         cudaFuncAttributeMaxDynamicSharedMemorySize, K2_SMEM);
    int g2 = (B + TS2 - 1) / TS2;
    fc_kernel<<<g2, K2T, K2_SMEM>>>(x, fc2_b, cp_w, cp_b, wdl_w, wdl_b,
                                    pc, (float*)d_out, B);
}

// round 9
// speedup vs baseline: 1.2630x; 1.2630x over previous
#include <cuda_runtime.h>
#include <cuda_fp16.h>
#include <cstdint>

// ---------------------------------------------------------------------------
// EvalNet: EmbeddingBag(sum,pad) -> screlu -> fc2(1024->32) -> screlu
//          -> bucketed cp/wdl heads.   (sm_100 SIMT)
// P : emb fp32->fp16 (769 blocks); g_wdup[c][j]=(w,w) build (64 blocks,
//     coalesced).
// K1: 128-col chunked SMEM gather over fp16 table (R6 version, depth-1
//     HADD2); h written PAIR-INTERLEAVED fp32.
// K2: cp.async double-buffered fc2 (R5 structure, 256 thr) with pre-dup'd
//     weight pairs staged via cp16; sample-pair FFMA2; bucketed heads.
// ---------------------------------------------------------------------------

#define HIDDEN   1024
#define NROWS    769
#define MAX_B    16384
#define TILE     32

#define CHUNK1   128
#define NCHUNKS1 (HIDDEN / CHUNK1)   // 8
#define NGROUPS1 18                  // 8*18 = 144 blocks
#define K1T      512

#define K2T      256
#define TS2      64                  // samples per K2 block
#define CHUNK2   64
#define NCH2     (HIDDEN / CHUNK2)   // 16

__device__ float  g_h[(size_t)MAX_B * HIDDEN];   // pair-interleaved hidden
__device__ __half g_emb_h[NROWS * HIDDEN];       // fp16 table
__device__ float2 g_wdup[HIDDEN * 32];           // [c][j] = (w[j][c], w[j][c])

__device__ __forceinline__ float screlu1(float v)
{
    float c = fminf(fmaxf(v, 0.0f), 1.0f);
    return c * c;
}

__device__ __forceinline__ void fma2(unsigned long long& acc,
                                     unsigned long long a,
                                     unsigned long long b)
{
    asm("fma.rn.f32x2 %0, %1, %2, %0;" : "+l"(acc) : "l"(a), "l"(b));
}

__device__ __forceinline__ void add2(unsigned long long& acc,
                                     unsigned long long v)
{
    asm("add.rn.f32x2 %0, %0, %1;" : "+l"(acc) : "l"(v));
}

__device__ __forceinline__ uint32_t smem_u32(const void* p)
{
    uint32_t a;
    asm("{ .reg .u64 t; cvta.to.shared.u64 t, %1; cvt.u32.u64 %0, t; }"
        : "=r"(a) : "l"(p));
    return a;
}

__device__ __forceinline__ void cp_async16(uint32_t dst, const void* src)
{
    asm volatile("cp.async.ca.shared.global [%0], [%1], 16;"
                 :: "r"(dst), "l"(__cvta_generic_to_global(src)));
}

#define CP_COMMIT() asm volatile("cp.async.commit_group;" ::: "memory")
#define CP_WAIT0()  asm volatile("cp.async.wait_group 0;" ::: "memory")

union F2U { float2 f; unsigned long long u; };

// ---------------------------------------------------------------------------
// P: prep — blocks 0..768: emb row -> fp16; blocks 769..832: wdup build.
// ---------------------------------------------------------------------------
__global__ __launch_bounds__(512)
void prep_kernel(const float* __restrict__ emb,
                 const float* __restrict__ fc2_w)
{
    const int b = blockIdx.x, tid = threadIdx.x;
    if (b < NROWS) {
        const float2* src = (const float2*)(emb + b * HIDDEN);
        __half2* dst = (__half2*)(g_emb_h + b * HIDDEN);
        dst[tid] = __floats2half2_rn(src[tid].x, src[tid].y);
    } else {
        // i over 32768 = HIDDEN*32 elements; writes fully coalesced.
        int i = (b - NROWS) * 512 + tid;
        int j = i & 31, c = i >> 5;
        float w = fc2_w[j * HIDDEN + c];
        g_wdup[i] = make_float2(w, w);
    }
}

// ---------------------------------------------------------------------------
// K1: gather + bias + screlu over a 128-col fp16 table slice (R6 version).
// ---------------------------------------------------------------------------
__global__ __launch_bounds__(K1T)
void gather_kernel(const void* __restrict__ xv,
                   const float* __restrict__ bias1,
                   int B)
{
    extern __shared__ char smem[];
    __half* s_tab  = (__half*)smem;                                  // NROWS*CHUNK1*2
    int*    s_idx  = (int*)(smem + NROWS * CHUNK1 * 2);              // 2*1024*4
    float*  s_bias = (float*)(smem + NROWS * CHUNK1 * 2 + 8192);     // CHUNK1*4
    int*    s_nz   = (int*)(smem + NROWS * CHUNK1 * 2 + 8192 + CHUNK1 * 4);

    const int tid   = threadIdx.x;
    const int cbase = blockIdx.x * CHUNK1;

    if (tid == 0) *s_nz = 0;
    __syncthreads();

    if (tid < 64) {
        if (((const unsigned int*)xv)[2 * tid + 1]) atomicOr(s_nz, 1);
    }

    {
        const uint4* src = (const uint4*)g_emb_h;       // row stride 128 uint4
        uint4*       dst = (uint4*)s_tab;               // row stride 16 uint4
        const int cb8 = cbase >> 3;
        for (int i = tid; i < NROWS * 16; i += K1T) {
            int row = i >> 4, u = i & 15;
            dst[i] = src[row * 128 + cb8 + u];
        }
    }
    if (tid < CHUNK1) s_bias[tid] = bias1[cbase + tid];
    __syncthreads();

    const int is64 = (*s_nz == 0);

    const int s   = tid >> 4;
    const int q   = tid & 15;
    const int odd = s & 1;

    const int spg     = (((B + NGROUPS1 - 1) / NGROUPS1) + TILE - 1) & ~(TILE - 1);
    const int s_begin = blockIdx.y * spg;
    const int s_end   = min(B, s_begin + spg);

    const int*       x32 = (const int*)xv;
    const long long* x64 = (const long long*)xv;
    float2*          ghp = (float2*)g_h;
    const uint4*     tab4 = (const uint4*)s_tab;

    int pre0 = NROWS - 1, pre1 = NROWS - 1;
    if (s_begin < s_end) {
        #pragma unroll
        for (int k = 0; k < 2; k++) {
            int j = tid + k * K1T;
            int samp = s_begin + (j >> 5);
            int v = NROWS - 1;
            if (samp < B) {
                int r = j & 31;
                v = is64 ? (int)x64[(size_t)samp * 32 + r]
                         : x32[samp * 32 + r];
            }
            if (k == 0) pre0 = v; else pre1 = v;
        }
    }

    int buf = 0;
    for (int t0 = s_begin; t0 < s_end; t0 += TILE) {
        s_idx[buf * 1024 + tid]       = pre0;
        s_idx[buf * 1024 + tid + K1T] = pre1;
        __syncthreads();

        int tn = t0 + TILE;
        if (tn < s_end) {
            #pragma unroll
            for (int k = 0; k < 2; k++) {
                int j = tid + k * K1T;
                int samp = tn + (j >> 5);
                int v = NROWS - 1;
                if (samp < B) {
                    int r = j & 31;
                    v = is64 ? (int)x64[(size_t)samp * 32 + r]
                             : x32[samp * 32 + r];
                }
                if (k == 0) pre0 = v; else pre1 = v;
            }
        }

        const int* idx = &s_idx[buf * 1024 + s * 32];

        unsigned long long a0 = 0ull, a1 = 0ull, a2 = 0ull, a3 = 0ull;
        #pragma unroll
        for (int r0 = 0; r0 < 32; r0 += 8) {
            int id[8];
            #pragma unroll
            for (int k = 0; k < 8; k++) id[k] = idx[r0 + k];
            uint4 v[8];
            #pragma unroll
            for (int k = 0; k < 8; k++) v[k] = tab4[id[k] * 16 + q];
            #pragma unroll
            for (int p = 0; p < 4; p++) {
                const uint4& va = v[2 * p];
                const uint4& vb = v[2 * p + 1];
                __half2 hx = __hadd2(*(const __half2*)&va.x, *(const __half2*)&vb.x);
                __half2 hy = __hadd2(*(const __half2*)&va.y, *(const __half2*)&vb.y);
                __half2 hz = __hadd2(*(const __half2*)&va.z, *(const __half2*)&vb.z);
                __half2 hw = __hadd2(*(const __half2*)&va.w, *(const __half2*)&vb.w);
                F2U f0, f1, f2, f3;
                f0.f = __half22float2(hx);
                f1.f = __half22float2(hy);
                f2.f = __half22float2(hz);
                f3.f = __half22float2(hw);
                add2(a0, f0.u);
                add2(a1, f1.u);
                add2(a2, f2.u);
                add2(a3, f3.u);
            }
        }

        int samp = t0 + s;

        float h[8];
        {
            F2U u0, u1, u2, u3;
            u0.u = a0; u1.u = a1; u2.u = a2; u3.u = a3;
            h[0] = u0.f.x; h[1] = u0.f.y; h[2] = u1.f.x; h[3] = u1.f.y;
            h[4] = u2.f.x; h[5] = u2.f.y; h[6] = u3.f.x; h[7] = u3.f.y;
            const float4 b0 = ((const float4*)s_bias)[2 * q];
            const float4 b1 = ((const float4*)s_bias)[2 * q + 1];
            h[0] = screlu1(h[0] + b0.x); h[1] = screlu1(h[1] + b0.y);
            h[2] = screlu1(h[2] + b0.z); h[3] = screlu1(h[3] + b0.w);
            h[4] = screlu1(h[4] + b1.x); h[5] = screlu1(h[5] + b1.y);
            h[6] = screlu1(h[6] + b1.z); h[7] = screlu1(h[7] + b1.w);
        }

        float p[8];
        #pragma unroll
        for (int k = 0; k < 8; k++)
            p[k] = __shfl_xor_sync(0xffffffffu, h[k], 16);

        if (samp < B) {
            size_t pr = (size_t)(samp >> 1);
            float2* base = ghp + pr * HIDDEN + cbase + 8 * q + odd * 4;
            if (!odd) {
                ((float4*)base)[0] = make_float4(h[0], p[0], h[1], p[1]);
                ((float4*)base)[1] = make_float4(h[2], p[2], h[3], p[3]);
            } else {
                ((float4*)base)[0] = make_float4(p[4], h[4], p[5], h[5]);
                ((float4*)base)[1] = make_float4(p[6], h[6], p[7], h[7]);
            }
        }
        buf ^= 1;
    }
}

// ---------------------------------------------------------------------------
// K2: fc2 via sample-pair FFMA2; cp.async double-buffered h + pre-dup'd w.
// 256 threads, 64 samples/block (R5 structure). jq = tid&15 owns j {2jq,
// 2jq+1}; sg = tid>>4 owns pairs {2sg, 2sg+1}.
// ---------------------------------------------------------------------------
#define K2_OFF_H    0
#define K2_HBUF     16384              // 32 pairs * 64 ull * 8
#define K2_OFF_W    32768
#define K2_WBUF     16384              // 64 c * 32 j * 8 (dup pairs)
#define K2_OFF_CPW  65536
#define K2_OFF_WDLW 66560
#define K2_OFF_FB   69632
#define K2_OFF_CB   69760
#define K2_OFF_WB   69792
#define K2_OFF_NZ   69888
#define K2_SMEM     69904

__global__ __launch_bounds__(K2T)
void fc_kernel(const void* __restrict__ xv,
               const float* __restrict__ fc2_b,
               const float* __restrict__ cp_w,  const float* __restrict__ cp_b,
               const float* __restrict__ wdl_w, const float* __restrict__ wdl_b,
               const void* __restrict__ pcv, float* __restrict__ out, int B)
{
    extern __shared__ char smem[];
    const uint32_t sbase = smem_u32(smem);

    float* s_cp_w  = (float*)(smem + K2_OFF_CPW);
    float* s_wdl_w = (float*)(smem + K2_OFF_WDLW);
    float* s_fc2_b = (float*)(smem + K2_OFF_FB);
    float* s_cp_b  = (float*)(smem + K2_OFF_CB);
    float* s_wdl_b = (float*)(smem + K2_OFF_WB);
    int*   s_nz    = (int*)(smem + K2_OFF_NZ);

    const int tid = threadIdx.x;
    const int s0  = blockIdx.x * TS2;
    const int p0  = s0 >> 1;

    if (tid == 0) *s_nz = 0;
    __syncthreads();
    if (tid < 64) {
        if (((const unsigned int*)xv)[2 * tid + 1]) atomicOr(s_nz, 1);
    }
    for (int i = tid; i < 8 * 32; i += K2T)  s_cp_w[i]  = cp_w[i];
    for (int i = tid; i < 24 * 32; i += K2T) s_wdl_w[i] = wdl_w[i];
    if (tid < 32) s_fc2_b[tid] = fc2_b[tid];
    if (tid < 8)  s_cp_b[tid]  = cp_b[tid];
    if (tid < 24) s_wdl_b[tid] = wdl_b[tid];

    const float2* ghp = (const float2*)g_h;

    auto stage = [&](int k) {
        int buf = k & 1;
        int c0  = k * CHUNK2;
        uint32_t hdst = sbase + K2_OFF_H + buf * K2_HBUF;
        uint32_t wdst = sbase + K2_OFF_W + buf * K2_WBUF;
        // h: 32 pair-rows x 64 c = 1024 cp16
        #pragma unroll
        for (int r = 0; r < 4; r++) {
            int u   = tid + r * K2T;
            int p   = u >> 5;            // pair row 0..31
            int c16 = u & 31;            // 16B unit within row
            cp_async16(hdst + (uint32_t)(p * 512 + c16 * 16),
                       ghp + ((size_t)(p0 + p) * HIDDEN + c0 + c16 * 2));
        }
        // wdup chunk: contiguous 16KB
        const char* wsrc = (const char*)(g_wdup + (size_t)c0 * 32);
        #pragma unroll
        for (int r = 0; r < 4; r++) {
            int u = tid + r * K2T;
            cp_async16(wdst + (uint32_t)(u * 16), wsrc + u * 16);
        }
        CP_COMMIT();
    };

    stage(0);

    const int jq = tid & 15;     // j = 2jq, 2jq+1
    const int sg = tid >> 4;     // pairs 2sg, 2sg+1

    unsigned long long acc00 = 0ull, acc01 = 0ull, acc10 = 0ull, acc11 = 0ull;

    for (int k = 0; k < NCH2; k++) {
        CP_WAIT0();
        __syncthreads();
        if (k + 1 < NCH2) stage(k + 1);   // overlaps compute below

        int buf = k & 1;
        const unsigned long long* hb =
            (const unsigned long long*)(smem + K2_OFF_H + buf * K2_HBUF);
        const ulonglong2* wb2 =
            (const ulonglong2*)(smem + K2_OFF_W + buf * K2_WBUF);
        const unsigned long long* h0 = hb + (2 * sg) * CHUNK2;
        const unsigned long long* h1 = hb + (2 * sg + 1) * CHUNK2;

        #pragma unroll 8
        for (int c = 0; c < CHUNK2; c++) {
            unsigned long long hv0 = h0[c];
            unsigned long long hv1 = h1[c];
            ulonglong2 ww = wb2[c * 16 + jq];   // (w2jq,w2jq) , (w2jq+1,w2jq+1)
            fma2(acc00, hv0, ww.x);
            fma2(acc01, hv0, ww.y);
            fma2(acc10, hv1, ww.x);
            fma2(acc11, hv1, ww.y);
        }
        __syncthreads();
    }

    // h2 = screlu(acc + b) into smem (reuse hbuf: 64*33*4 = 8448 B)
    float* s_h2 = (float*)(smem + K2_OFF_H);
    {
        unsigned long long accs[2][2] = {{acc00, acc01}, {acc10, acc11}};
        #pragma unroll
        for (int p = 0; p < 2; p++) {
            #pragma unroll
            for (int jj = 0; jj < 2; jj++) {
                int j = 2 * jq + jj;
                F2U u; u.u = accs[p][jj];
                s_h2[(4 * sg + 2 * p)     * 33 + j] = screlu1(u.f.x + s_fc2_b[j]);
                s_h2[(4 * sg + 2 * p + 1) * 33 + j] = screlu1(u.f.y + s_fc2_b[j]);
            }
        }
    }
    __syncthreads();

    // heads: one thread per sample
    if (tid < TS2) {
        int samp = s0 + tid;
        if (samp < B) {
            const int is64 = (*s_nz == 0);
            int pc = is64 ? (int)((const long long*)pcv)[samp]
                          : ((const int*)pcv)[samp];
            int bkt = (pc - 2) * 8 / 30;
            bkt = max(0, min(7, bkt));

            const float* h2 = &s_h2[tid * 33];
            float cp = s_cp_b[bkt];
            float w0 = s_wdl_b[bkt * 3 + 0];
            float w1 = s_wdl_b[bkt * 3 + 1];
            float w2 = s_wdl_b[bkt * 3 + 2];
            const float* cw  = &s_cp_w[bkt * 32];
            const float* ww0 = &s_wdl_w[(bkt * 3 + 0) * 32];
            const float* ww1 = &s_wdl_w[(bkt * 3 + 1) * 32];
            const float* ww2 = &s_wdl_w[(bkt * 3 + 2) * 32];
            #pragma unroll
            for (int j = 0; j < 32; j++) {
                float hh = h2[j];
                cp = fmaf(hh, cw[j],  cp);
                w0 = fmaf(hh, ww0[j], w0);
                w1 = fmaf(hh, ww1[j], w1);
                w2 = fmaf(hh, ww2[j], w2);
            }
            out[samp] = cp;
            out[B + samp * 3 + 0] = w0;
            out[B + samp * 3 + 1] = w1;
            out[B + samp * 3 + 2] = w2;
        }
    }
}

// ---------------------------------------------------------------------------
extern "C" void kernel_launch(void* const* d_in, const int* in_sizes, int n_in,
                              void* d_out, int out_size)
{
    const void*  x      = d_in[0];
    const void*  pc     = d_in[1];
    const float* emb    = (const float*)d_in[2];
    const float* bias1  = (const float*)d_in[3];
    const float* fc2_w  = (const float*)d_in[4];
    const float* fc2_b  = (const float*)d_in[5];
    const float* cp_w   = (const float*)d_in[6];
    const float* cp_b   = (const float*)d_in[7];
    const float* wdl_w  = (const float*)d_in[8];
    const float* wdl_b  = (const float*)d_in[9];

    int B = in_sizes[0] / 32;
    if (B > MAX_B) B = MAX_B;

    prep_kernel<<<NROWS + 64, 512>>>(emb, fc2_w);

    const int k1_smem = NROWS * CHUNK1 * 2 + 8192 + CHUNK1 * 4 + 16;
    cudaFuncSetAttribute(gather_kernel,
                         cudaFuncAttributeMaxDynamicSharedMemorySize, k1_smem);
    dim3 g1(NCHUNKS1, NGROUPS1);
    gather_kernel<<<g1, K1T, k1_smem>>>(x, bias1, B);

    cudaFuncSetAttribute(fc_kernel,
                         cudaFuncAttributeMaxDynamicSharedMemorySize, K2_SMEM);
    int g2 = (B + TS2 - 1) / TS2;
    fc_kernel<<<g2, K2T, K2_SMEM>>>(x, fc2_b, cp_w, cp_b, wdl_w, wdl_b,
                                    pc, (float*)d_out, B);
}

// round 10
// speedup vs baseline: 1.2827x; 1.0156x over previous
#include <cuda_runtime.h>
#include <cuda_fp16.h>
#include <cstdint>

// ---------------------------------------------------------------------------
// EvalNet: EmbeddingBag(sum,pad) -> screlu -> fc2(1024->32) -> screlu
//          -> bucketed cp/wdl heads.   (sm_100 SIMT)
// P : emb fp32->fp16 (769 blocks).
// K1: 128-col chunked SMEM gather over fp16 table (R6 version); h written
//     PAIR-INTERLEAVED fp32.
// K2: R6 structure, but TS2=32 / grid=512 for occupancy: cp.async
//     double-buffered h + transposed w, 1-pair x 2-j FFMA2 per thread.
// ---------------------------------------------------------------------------

#define HIDDEN   1024
#define NROWS    769
#define MAX_B    16384
#define TILE     32

#define CHUNK1   128
#define NCHUNKS1 (HIDDEN / CHUNK1)   // 8
#define NGROUPS1 18                  // 8*18 = 144 blocks
#define K1T      512

#define K2T      256
#define TS2      32                  // samples per K2 block
#define CHUNK2   64
#define NCH2     (HIDDEN / CHUNK2)   // 16
#define WT_STRIDE 33

__device__ float  g_h[(size_t)MAX_B * HIDDEN];   // pair-interleaved hidden
__device__ __half g_emb_h[NROWS * HIDDEN];       // fp16 table

__device__ __forceinline__ float screlu1(float v)
{
    float c = fminf(fmaxf(v, 0.0f), 1.0f);
    return c * c;
}

__device__ __forceinline__ void fma2(unsigned long long& acc,
                                     unsigned long long a,
                                     unsigned long long b)
{
    asm("fma.rn.f32x2 %0, %1, %2, %0;" : "+l"(acc) : "l"(a), "l"(b));
}

__device__ __forceinline__ void add2(unsigned long long& acc,
                                     unsigned long long v)
{
    asm("add.rn.f32x2 %0, %0, %1;" : "+l"(acc) : "l"(v));
}

__device__ __forceinline__ unsigned long long packdup(float w)
{
    unsigned long long r;
    asm("mov.b64 %0, {%1, %1};" : "=l"(r) : "f"(w));
    return r;
}

__device__ __forceinline__ uint32_t smem_u32(const void* p)
{
    uint32_t a;
    asm("{ .reg .u64 t; cvta.to.shared.u64 t, %1; cvt.u32.u64 %0, t; }"
        : "=r"(a) : "l"(p));
    return a;
}

__device__ __forceinline__ void cp_async16(uint32_t dst, const void* src)
{
    asm volatile("cp.async.ca.shared.global [%0], [%1], 16;"
                 :: "r"(dst), "l"(__cvta_generic_to_global(src)));
}

__device__ __forceinline__ void cp_async4(uint32_t dst, const void* src)
{
    asm volatile("cp.async.ca.shared.global [%0], [%1], 4;"
                 :: "r"(dst), "l"(__cvta_generic_to_global(src)));
}

#define CP_COMMIT() asm volatile("cp.async.commit_group;" ::: "memory")
#define CP_WAIT0()  asm volatile("cp.async.wait_group 0;" ::: "memory")

union F2U { float2 f; unsigned long long u; };

// ---------------------------------------------------------------------------
// P: emb fp32 -> fp16.
// ---------------------------------------------------------------------------
__global__ __launch_bounds__(512)
void prep_kernel(const float* __restrict__ emb)
{
    const int b = blockIdx.x, tid = threadIdx.x;
    const float2* src = (const float2*)(emb + b * HIDDEN);
    __half2* dst = (__half2*)(g_emb_h + b * HIDDEN);
    dst[tid] = __floats2half2_rn(src[tid].x, src[tid].y);
}

// ---------------------------------------------------------------------------
// K1: gather + bias + screlu over a 128-col fp16 table slice (R6 version).
// ---------------------------------------------------------------------------
__global__ __launch_bounds__(K1T)
void gather_kernel(const void* __restrict__ xv,
                   const float* __restrict__ bias1,
                   int B)
{
    extern __shared__ char smem[];
    __half* s_tab  = (__half*)smem;                                  // NROWS*CHUNK1*2
    int*    s_idx  = (int*)(smem + NROWS * CHUNK1 * 2);              // 2*1024*4
    float*  s_bias = (float*)(smem + NROWS * CHUNK1 * 2 + 8192);     // CHUNK1*4
    int*    s_nz   = (int*)(smem + NROWS * CHUNK1 * 2 + 8192 + CHUNK1 * 4);

    const int tid   = threadIdx.x;
    const int cbase = blockIdx.x * CHUNK1;

    if (tid == 0) *s_nz = 0;
    __syncthreads();

    if (tid < 64) {
        if (((const unsigned int*)xv)[2 * tid + 1]) atomicOr(s_nz, 1);
    }

    {
        const uint4* src = (const uint4*)g_emb_h;       // row stride 128 uint4
        uint4*       dst = (uint4*)s_tab;               // row stride 16 uint4
        const int cb8 = cbase >> 3;
        for (int i = tid; i < NROWS * 16; i += K1T) {
            int row = i >> 4, u = i & 15;
            dst[i] = src[row * 128 + cb8 + u];
        }
    }
    if (tid < CHUNK1) s_bias[tid] = bias1[cbase + tid];
    __syncthreads();

    const int is64 = (*s_nz == 0);

    const int s   = tid >> 4;
    const int q   = tid & 15;
    const int odd = s & 1;

    const int spg     = (((B + NGROUPS1 - 1) / NGROUPS1) + TILE - 1) & ~(TILE - 1);
    const int s_begin = blockIdx.y * spg;
    const int s_end   = min(B, s_begin + spg);

    const int*       x32 = (const int*)xv;
    const long long* x64 = (const long long*)xv;
    float2*          ghp = (float2*)g_h;
    const uint4*     tab4 = (const uint4*)s_tab;

    int pre0 = NROWS - 1, pre1 = NROWS - 1;
    if (s_begin < s_end) {
        #pragma unroll
        for (int k = 0; k < 2; k++) {
            int j = tid + k * K1T;
            int samp = s_begin + (j >> 5);
            int v = NROWS - 1;
            if (samp < B) {
                int r = j & 31;
                v = is64 ? (int)x64[(size_t)samp * 32 + r]
                         : x32[samp * 32 + r];
            }
            if (k == 0) pre0 = v; else pre1 = v;
        }
    }

    int buf = 0;
    for (int t0 = s_begin; t0 < s_end; t0 += TILE) {
        s_idx[buf * 1024 + tid]       = pre0;
        s_idx[buf * 1024 + tid + K1T] = pre1;
        __syncthreads();

        int tn = t0 + TILE;
        if (tn < s_end) {
            #pragma unroll
            for (int k = 0; k < 2; k++) {
                int j = tid + k * K1T;
                int samp = tn + (j >> 5);
                int v = NROWS - 1;
                if (samp < B) {
                    int r = j & 31;
                    v = is64 ? (int)x64[(size_t)samp * 32 + r]
                             : x32[samp * 32 + r];
                }
                if (k == 0) pre0 = v; else pre1 = v;
            }
        }

        const int* idx = &s_idx[buf * 1024 + s * 32];

        unsigned long long a0 = 0ull, a1 = 0ull, a2 = 0ull, a3 = 0ull;
        #pragma unroll
        for (int r0 = 0; r0 < 32; r0 += 8) {
            int id[8];
            #pragma unroll
            for (int k = 0; k < 8; k++) id[k] = idx[r0 + k];
            uint4 v[8];
            #pragma unroll
            for (int k = 0; k < 8; k++) v[k] = tab4[id[k] * 16 + q];
            #pragma unroll
            for (int p = 0; p < 4; p++) {
                const uint4& va = v[2 * p];
                const uint4& vb = v[2 * p + 1];
                __half2 hx = __hadd2(*(const __half2*)&va.x, *(const __half2*)&vb.x);
                __half2 hy = __hadd2(*(const __half2*)&va.y, *(const __half2*)&vb.y);
                __half2 hz = __hadd2(*(const __half2*)&va.z, *(const __half2*)&vb.z);
                __half2 hw = __hadd2(*(const __half2*)&va.w, *(const __half2*)&vb.w);
                F2U f0, f1, f2, f3;
                f0.f = __half22float2(hx);
                f1.f = __half22float2(hy);
                f2.f = __half22float2(hz);
                f3.f = __half22float2(hw);
                add2(a0, f0.u);
                add2(a1, f1.u);
                add2(a2, f2.u);
                add2(a3, f3.u);
            }
        }

        int samp = t0 + s;

        float h[8];
        {
            F2U u0, u1, u2, u3;
            u0.u = a0; u1.u = a1; u2.u = a2; u3.u = a3;
            h[0] = u0.f.x; h[1] = u0.f.y; h[2] = u1.f.x; h[3] = u1.f.y;
            h[4] = u2.f.x; h[5] = u2.f.y; h[6] = u3.f.x; h[7] = u3.f.y;
            const float4 b0 = ((const float4*)s_bias)[2 * q];
            const float4 b1 = ((const float4*)s_bias)[2 * q + 1];
            h[0] = screlu1(h[0] + b0.x); h[1] = screlu1(h[1] + b0.y);
            h[2] = screlu1(h[2] + b0.z); h[3] = screlu1(h[3] + b0.w);
            h[4] = screlu1(h[4] + b1.x); h[5] = screlu1(h[5] + b1.y);
            h[6] = screlu1(h[6] + b1.z); h[7] = screlu1(h[7] + b1.w);
        }

        float p[8];
        #pragma unroll
        for (int k = 0; k < 8; k++)
            p[k] = __shfl_xor_sync(0xffffffffu, h[k], 16);

        if (samp < B) {
            size_t pr = (size_t)(samp >> 1);
            float2* base = ghp + pr * HIDDEN + cbase + 8 * q + odd * 4;
            if (!odd) {
                ((float4*)base)[0] = make_float4(h[0], p[0], h[1], p[1]);
                ((float4*)base)[1] = make_float4(h[2], p[2], h[3], p[3]);
            } else {
                ((float4*)base)[0] = make_float4(p[4], h[4], p[5], h[5]);
                ((float4*)base)[1] = make_float4(p[6], h[6], p[7], h[7]);
            }
        }
        buf ^= 1;
    }
}

// ---------------------------------------------------------------------------
// K2: fc2 via sample-pair FFMA2; cp.async double-buffered h + transposed w.
// 256 threads, 32 samples/block (grid = B/32 = 512 for occupancy).
// pg = tid>>4 owns pair pg (samples 2pg, 2pg+1); jq = tid&15 owns j {2jq,
// 2jq+1}.  Inner loop shape identical to R6 (scalar weight broadcast).
// ---------------------------------------------------------------------------
#define K2_OFF_H    0
#define K2_HBUF     8192               // 16 pairs * 64 ull * 8
#define K2_OFF_W    16384
#define K2_WBUF     8448               // 64 c * 33 stride * 4
#define K2_OFF_CPW  33280
#define K2_OFF_WDLW 34304
#define K2_OFF_FB   37376
#define K2_OFF_CB   37504
#define K2_OFF_WB   37536
#define K2_OFF_NZ   37632
#define K2_SMEM     37648

__global__ __launch_bounds__(K2T)
void fc_kernel(const void* __restrict__ xv,
               const float* __restrict__ fc2_w, const float* __restrict__ fc2_b,
               const float* __restrict__ cp_w,  const float* __restrict__ cp_b,
               const float* __restrict__ wdl_w, const float* __restrict__ wdl_b,
               const void* __restrict__ pcv, float* __restrict__ out, int B)
{
    extern __shared__ char smem[];
    const uint32_t sbase = smem_u32(smem);

    float* s_cp_w  = (float*)(smem + K2_OFF_CPW);
    float* s_wdl_w = (float*)(smem + K2_OFF_WDLW);
    float* s_fc2_b = (float*)(smem + K2_OFF_FB);
    float* s_cp_b  = (float*)(smem + K2_OFF_CB);
    float* s_wdl_b = (float*)(smem + K2_OFF_WB);
    int*   s_nz    = (int*)(smem + K2_OFF_NZ);

    const int tid = threadIdx.x;
    const int s0  = blockIdx.x * TS2;
    const int p0  = s0 >> 1;             // first pair row (16 pairs/block)

    if (tid == 0) *s_nz = 0;
    __syncthreads();
    if (tid < 64) {
        if (((const unsigned int*)xv)[2 * tid + 1]) atomicOr(s_nz, 1);
    }
    for (int i = tid; i < 8 * 32; i += K2T)  s_cp_w[i]  = cp_w[i];
    for (int i = tid; i < 24 * 32; i += K2T) s_wdl_w[i] = wdl_w[i];
    if (tid < 32) s_fc2_b[tid] = fc2_b[tid];
    if (tid < 8)  s_cp_b[tid]  = cp_b[tid];
    if (tid < 24) s_wdl_b[tid] = wdl_b[tid];

    const float2* ghp = (const float2*)g_h;

    auto stage = [&](int k) {
        int buf = k & 1;
        int c0  = k * CHUNK2;
        uint32_t hdst = sbase + K2_OFF_H + buf * K2_HBUF;
        uint32_t wdst = sbase + K2_OFF_W + buf * K2_WBUF;
        // h: 16 pair-rows x 64 c = 512 cp16
        #pragma unroll
        for (int r = 0; r < 2; r++) {
            int u   = tid + r * K2T;
            int p   = u >> 5;            // pair row 0..15
            int c16 = u & 31;            // 16B unit within row
            cp_async16(hdst + (uint32_t)(p * 512 + c16 * 16),
                       ghp + ((size_t)(p0 + p) * HIDDEN + c0 + c16 * 2));
        }
        // w transposed: wt[c*33 + j] = fc2_w[j][c0+c]
        #pragma unroll
        for (int r = 0; r < 8; r++) {
            int u = tid + r * K2T;
            int j = u >> 6;              // 0..31
            int c = u & 63;              // 0..63
            cp_async4(wdst + (uint32_t)((c * WT_STRIDE + j) * 4),
                      fc2_w + j * HIDDEN + c0 + c);
        }
        CP_COMMIT();
    };

    stage(0);

    const int jq = tid & 15;     // j = 2jq, 2jq+1
    const int pg = tid >> 4;     // pair pg (samples 2pg, 2pg+1)

    unsigned long long acc0 = 0ull, acc1 = 0ull;

    for (int k = 0; k < NCH2; k++) {
        CP_WAIT0();
        __syncthreads();
        if (k + 1 < NCH2) stage(k + 1);   // overlaps compute below

        int buf = k & 1;
        const unsigned long long* hb =
            (const unsigned long long*)(smem + K2_OFF_H + buf * K2_HBUF);
        const float* wb = (const float*)(smem + K2_OFF_W + buf * K2_WBUF);
        const unsigned long long* h0 = hb + pg * CHUNK2;

        #pragma unroll 8
        for (int c = 0; c < CHUNK2; c++) {
            unsigned long long hv = h0[c];
            unsigned long long W0 = packdup(wb[c * WT_STRIDE + 2 * jq]);
            unsigned long long W1 = packdup(wb[c * WT_STRIDE + 2 * jq + 1]);
            fma2(acc0, hv, W0);
            fma2(acc1, hv, W1);
        }
        __syncthreads();
    }

    // h2 = screlu(acc + b) into smem (reuse hbuf: 32*33*4 = 4224 B)
    float* s_h2 = (float*)(smem + K2_OFF_H);
    {
        unsigned long long accs[2] = {acc0, acc1};
        #pragma unroll
        for (int jj = 0; jj < 2; jj++) {
            int j = 2 * jq + jj;
            F2U u; u.u = accs[jj];
            s_h2[(2 * pg)     * 33 + j] = screlu1(u.f.x + s_fc2_b[j]);
            s_h2[(2 * pg + 1) * 33 + j] = screlu1(u.f.y + s_fc2_b[j]);
        }
    }
    __syncthreads();

    // heads: one thread per sample
    if (tid < TS2) {
        int samp = s0 + tid;
        if (samp < B) {
            const int is64 = (*s_nz == 0);
            int pc = is64 ? (int)((const long long*)pcv)[samp]
                          : ((const int*)pcv)[samp];
            int bkt = (pc - 2) * 8 / 30;
            bkt = max(0, min(7, bkt));

            const float* h2 = &s_h2[tid * 33];
            float cp = s_cp_b[bkt];
            float w0 = s_wdl_b[bkt * 3 + 0];
            float w1 = s_wdl_b[bkt * 3 + 1];
            float w2 = s_wdl_b[bkt * 3 + 2];
            const float* cw  = &s_cp_w[bkt * 32];
            const float* ww0 = &s_wdl_w[(bkt * 3 + 0) * 32];
            const float* ww1 = &s_wdl_w[(bkt * 3 + 1) * 32];
            const float* ww2 = &s_wdl_w[(bkt * 3 + 2) * 32];
            #pragma unroll
            for (int j = 0; j < 32; j++) {
                float hh = h2[j];
                cp = fmaf(hh, cw[j],  cp);
                w0 = fmaf(hh, ww0[j], w0);
                w1 = fmaf(hh, ww1[j], w1);
                w2 = fmaf(hh, ww2[j], w2);
            }
            out[samp] = cp;
            out[B + samp * 3 + 0] = w0;
            out[B + samp * 3 + 1] = w1;
            out[B + samp * 3 + 2] = w2;
        }
    }
}

// ---------------------------------------------------------------------------
extern "C" void kernel_launch(void* const* d_in, const int* in_sizes, int n_in,
                              void* d_out, int out_size)
{
    const void*  x      = d_in[0];
    const void*  pc     = d_in[1];
    const float* emb    = (const float*)d_in[2];
    const float* bias1  = (const float*)d_in[3];
    const float* fc2_w  = (const float*)d_in[4];
    const float* fc2_b  = (const float*)d_in[5];
    const float* cp_w   = (const float*)d_in[6];
    const float* cp_b   = (const float*)d_in[7];
    const float* wdl_w  = (const float*)d_in[8];
    const float* wdl_b  = (const float*)d_in[9];

    int B = in_sizes[0] / 32;
    if (B > MAX_B) B = MAX_B;

    prep_kernel<<<NROWS, 512>>>(emb);

    const int k1_smem = NROWS * CHUNK1 * 2 + 8192 + CHUNK1 * 4 + 16;
    cudaFuncSetAttribute(gather_kernel,
                         cudaFuncAttributeMaxDynamicSharedMemorySize, k1_smem);
    dim3 g1(NCHUNKS1, NGROUPS1);
    gather_kernel<<<g1, K1T, k1_smem>>>(x, bias1, B);

    cudaFuncSetAttribute(fc_kernel,
                         cudaFuncAttributeMaxDynamicSharedMemorySize, K2_SMEM);
    int g2 = (B + TS2 - 1) / TS2;
    fc_kernel<<<g2, K2T, K2_SMEM>>>(x, fc2_w, fc2_b, cp_w, cp_b, wdl_w, wdl_b,
                                    pc, (float*)d_out, B);
}

// round 11
// speedup vs baseline: 1.4994x; 1.1689x over previous
#include <cuda_runtime.h>
#include <cuda_fp16.h>
#include <cstdint>

// ---------------------------------------------------------------------------
// EvalNet: EmbeddingBag(sum,pad) -> screlu -> fc2(1024->32) -> screlu
//          -> bucketed cp/wdl heads.   (sm_100 SIMT)
// P : emb fp32->fp16 (769 blocks); w transpose g_wT[c*32+j] (64 blocks).
// K1: R6 gather with depth-2 HADD2 tree; h PAIR-INTERLEAVED fp32.
// K2: R6 structure (TS2=64, 256 thr) with w staged as contiguous cp16 from
//     pre-transposed g_wT; scalar-broadcast FFMA2 inner loop.
// ---------------------------------------------------------------------------

#define HIDDEN   1024
#define NROWS    769
#define MAX_B    16384
#define TILE     32

#define CHUNK1   128
#define NCHUNKS1 (HIDDEN / CHUNK1)   // 8
#define NGROUPS1 18                  // 8*18 = 144 blocks
#define K1T      512

#define K2T      256
#define TS2      64                  // samples per K2 block (grid 256)
#define CHUNK2   64
#define NCH2     (HIDDEN / CHUNK2)   // 16

__device__ float  g_h[(size_t)MAX_B * HIDDEN];   // pair-interleaved hidden
__device__ __half g_emb_h[NROWS * HIDDEN];       // fp16 table
__device__ float  g_wT[HIDDEN * 32];             // wT[c*32+j] = fc2_w[j][c]

__device__ __forceinline__ float screlu1(float v)
{
    float c = fminf(fmaxf(v, 0.0f), 1.0f);
    return c * c;
}

__device__ __forceinline__ void fma2(unsigned long long& acc,
                                     unsigned long long a,
                                     unsigned long long b)
{
    asm("fma.rn.f32x2 %0, %1, %2, %0;" : "+l"(acc) : "l"(a), "l"(b));
}

__device__ __forceinline__ void add2(unsigned long long& acc,
                                     unsigned long long v)
{
    asm("add.rn.f32x2 %0, %0, %1;" : "+l"(acc) : "l"(v));
}

__device__ __forceinline__ unsigned long long packdup(float w)
{
    unsigned long long r;
    asm("mov.b64 %0, {%1, %1};" : "=l"(r) : "f"(w));
    return r;
}

__device__ __forceinline__ uint32_t smem_u32(const void* p)
{
    uint32_t a;
    asm("{ .reg .u64 t; cvta.to.shared.u64 t, %1; cvt.u32.u64 %0, t; }"
        : "=r"(a) : "l"(p));
    return a;
}

__device__ __forceinline__ void cp_async16(uint32_t dst, const void* src)
{
    asm volatile("cp.async.ca.shared.global [%0], [%1], 16;"
                 :: "r"(dst), "l"(__cvta_generic_to_global(src)));
}

#define CP_COMMIT() asm volatile("cp.async.commit_group;" ::: "memory")
#define CP_WAIT0()  asm volatile("cp.async.wait_group 0;" ::: "memory")

union F2U { float2 f; unsigned long long u; };

#define H2(u) (*(const __half2*)&(u))

// ---------------------------------------------------------------------------
// P: blocks 0..768: emb row -> fp16; blocks 769..832: wT build.
// ---------------------------------------------------------------------------
__global__ __launch_bounds__(512)
void prep_kernel(const float* __restrict__ emb,
                 const float* __restrict__ fc2_w)
{
    const int b = blockIdx.x, tid = threadIdx.x;
    if (b < NROWS) {
        const float2* src = (const float2*)(emb + b * HIDDEN);
        __half2* dst = (__half2*)(g_emb_h + b * HIDDEN);
        dst[tid] = __floats2half2_rn(src[tid].x, src[tid].y);
    } else {
        // i = j*1024 + c (coalesced reads); write g_wT[c*32 + j]
        int i = (b - NROWS) * 512 + tid;
        int j = i >> 10, c = i & 1023;
        g_wT[c * 32 + j] = fc2_w[i];
    }
}

// ---------------------------------------------------------------------------
// K1: gather + bias + screlu over a 128-col fp16 table slice.
// Depth-2 HADD2 tree (8 rows -> 2 fp16 partial sums) before f32x2 accumulate.
// ---------------------------------------------------------------------------
__global__ __launch_bounds__(K1T)
void gather_kernel(const void* __restrict__ xv,
                   const float* __restrict__ bias1,
                   int B)
{
    extern __shared__ char smem[];
    __half* s_tab  = (__half*)smem;                                  // NROWS*CHUNK1*2
    int*    s_idx  = (int*)(smem + NROWS * CHUNK1 * 2);              // 2*1024*4
    float*  s_bias = (float*)(smem + NROWS * CHUNK1 * 2 + 8192);     // CHUNK1*4
    int*    s_nz   = (int*)(smem + NROWS * CHUNK1 * 2 + 8192 + CHUNK1 * 4);

    const int tid   = threadIdx.x;
    const int cbase = blockIdx.x * CHUNK1;

    if (tid == 0) *s_nz = 0;
    __syncthreads();

    if (tid < 64) {
        if (((const unsigned int*)xv)[2 * tid + 1]) atomicOr(s_nz, 1);
    }

    {
        const uint4* src = (const uint4*)g_emb_h;       // row stride 128 uint4
        uint4*       dst = (uint4*)s_tab;               // row stride 16 uint4
        const int cb8 = cbase >> 3;
        for (int i = tid; i < NROWS * 16; i += K1T) {
            int row = i >> 4, u = i & 15;
            dst[i] = src[row * 128 + cb8 + u];
        }
    }
    if (tid < CHUNK1) s_bias[tid] = bias1[cbase + tid];
    __syncthreads();

    const int is64 = (*s_nz == 0);

    const int s   = tid >> 4;
    const int q   = tid & 15;
    const int odd = s & 1;

    const int spg     = (((B + NGROUPS1 - 1) / NGROUPS1) + TILE - 1) & ~(TILE - 1);
    const int s_begin = blockIdx.y * spg;
    const int s_end   = min(B, s_begin + spg);

    const int*       x32 = (const int*)xv;
    const long long* x64 = (const long long*)xv;
    float2*          ghp = (float2*)g_h;
    const uint4*     tab4 = (const uint4*)s_tab;

    int pre0 = NROWS - 1, pre1 = NROWS - 1;
    if (s_begin < s_end) {
        #pragma unroll
        for (int k = 0; k < 2; k++) {
            int j = tid + k * K1T;
            int samp = s_begin + (j >> 5);
            int v = NROWS - 1;
            if (samp < B) {
                int r = j & 31;
                v = is64 ? (int)x64[(size_t)samp * 32 + r]
                         : x32[samp * 32 + r];
            }
            if (k == 0) pre0 = v; else pre1 = v;
        }
    }

    int buf = 0;
    for (int t0 = s_begin; t0 < s_end; t0 += TILE) {
        s_idx[buf * 1024 + tid]       = pre0;
        s_idx[buf * 1024 + tid + K1T] = pre1;
        __syncthreads();

        int tn = t0 + TILE;
        if (tn < s_end) {
            #pragma unroll
            for (int k = 0; k < 2; k++) {
                int j = tid + k * K1T;
                int samp = tn + (j >> 5);
                int v = NROWS - 1;
                if (samp < B) {
                    int r = j & 31;
                    v = is64 ? (int)x64[(size_t)samp * 32 + r]
                             : x32[samp * 32 + r];
                }
                if (k == 0) pre0 = v; else pre1 = v;
            }
        }

        const int* idx = &s_idx[buf * 1024 + s * 32];

        unsigned long long a0 = 0ull, a1 = 0ull, a2 = 0ull, a3 = 0ull;
        #pragma unroll
        for (int r0 = 0; r0 < 32; r0 += 8) {
            int id[8];
            #pragma unroll
            for (int k = 0; k < 8; k++) id[k] = idx[r0 + k];
            uint4 v[8];
            #pragma unroll
            for (int k = 0; k < 8; k++) v[k] = tab4[id[k] * 16 + q];

            // depth-2 fp16 tree per component, then f32x2 accumulate
            #define TREE(COMP, ACC) do {                                         \
                __half2 d1 = __hadd2(__hadd2(H2(v[0].COMP), H2(v[1].COMP)),      \
                                     __hadd2(H2(v[2].COMP), H2(v[3].COMP)));     \
                __half2 d2 = __hadd2(__hadd2(H2(v[4].COMP), H2(v[5].COMP)),      \
                                     __hadd2(H2(v[6].COMP), H2(v[7].COMP)));     \
                F2U t1_, t2_;                                                    \
                t1_.f = __half22float2(d1);                                      \
                t2_.f = __half22float2(d2);                                      \
                add2(ACC, t1_.u);                                                \
                add2(ACC, t2_.u);                                                \
            } while (0)

            TREE(x, a0);
            TREE(y, a1);
            TREE(z, a2);
            TREE(w, a3);
            #undef TREE
        }

        int samp = t0 + s;

        float h[8];
        {
            F2U u0, u1, u2, u3;
            u0.u = a0; u1.u = a1; u2.u = a2; u3.u = a3;
            h[0] = u0.f.x; h[1] = u0.f.y; h[2] = u1.f.x; h[3] = u1.f.y;
            h[4] = u2.f.x; h[5] = u2.f.y; h[6] = u3.f.x; h[7] = u3.f.y;
            const float4 b0 = ((const float4*)s_bias)[2 * q];
            const float4 b1 = ((const float4*)s_bias)[2 * q + 1];
            h[0] = screlu1(h[0] + b0.x); h[1] = screlu1(h[1] + b0.y);
            h[2] = screlu1(h[2] + b0.z); h[3] = screlu1(h[3] + b0.w);
            h[4] = screlu1(h[4] + b1.x); h[5] = screlu1(h[5] + b1.y);
            h[6] = screlu1(h[6] + b1.z); h[7] = screlu1(h[7] + b1.w);
        }

        float p[8];
        #pragma unroll
        for (int k = 0; k < 8; k++)
            p[k] = __shfl_xor_sync(0xffffffffu, h[k], 16);

        if (samp < B) {
            size_t pr = (size_t)(samp >> 1);
            float2* base = ghp + pr * HIDDEN + cbase + 8 * q + odd * 4;
            if (!odd) {
                ((float4*)base)[0] = make_float4(h[0], p[0], h[1], p[1]);
                ((float4*)base)[1] = make_float4(h[2], p[2], h[3], p[3]);
            } else {
                ((float4*)base)[0] = make_float4(p[4], h[4], p[5], h[5]);
                ((float4*)base)[1] = make_float4(p[6], h[6], p[7], h[7]);
            }
        }
        buf ^= 1;
    }
}

// ---------------------------------------------------------------------------
// K2: fc2 via sample-pair FFMA2; cp.async double-buffered h + pre-transposed
// w (contiguous cp16 staging). 256 threads, 64 samples/block (R6 structure).
// jq = tid&15 owns j {2jq, 2jq+1}; sg = tid>>4 owns pairs {2sg, 2sg+1}.
// ---------------------------------------------------------------------------
#define K2_OFF_H    0
#define K2_HBUF     16384              // 32 pairs * 64 ull * 8
#define K2_OFF_W    32768
#define K2_WBUF     8192               // 64 c * 32 j * 4
#define K2_OFF_CPW  49152
#define K2_OFF_WDLW 50176
#define K2_OFF_FB   53248
#define K2_OFF_CB   53376
#define K2_OFF_WB   53408
#define K2_OFF_NZ   53504
#define K2_SMEM     53520

__global__ __launch_bounds__(K2T)
void fc_kernel(const void* __restrict__ xv,
               const float* __restrict__ fc2_b,
               const float* __restrict__ cp_w,  const float* __restrict__ cp_b,
               const float* __restrict__ wdl_w, const float* __restrict__ wdl_b,
               const void* __restrict__ pcv, float* __restrict__ out, int B)
{
    extern __shared__ char smem[];
    const uint32_t sbase = smem_u32(smem);

    float* s_cp_w  = (float*)(smem + K2_OFF_CPW);
    float* s_wdl_w = (float*)(smem + K2_OFF_WDLW);
    float* s_fc2_b = (float*)(smem + K2_OFF_FB);
    float* s_cp_b  = (float*)(smem + K2_OFF_CB);
    float* s_wdl_b = (float*)(smem + K2_OFF_WB);
    int*   s_nz    = (int*)(smem + K2_OFF_NZ);

    const int tid = threadIdx.x;
    const int s0  = blockIdx.x * TS2;
    const int p0  = s0 >> 1;

    if (tid == 0) *s_nz = 0;
    __syncthreads();
    if (tid < 64) {
        if (((const unsigned int*)xv)[2 * tid + 1]) atomicOr(s_nz, 1);
    }
    for (int i = tid; i < 8 * 32; i += K2T)  s_cp_w[i]  = cp_w[i];
    for (int i = tid; i < 24 * 32; i += K2T) s_wdl_w[i] = wdl_w[i];
    if (tid < 32) s_fc2_b[tid] = fc2_b[tid];
    if (tid < 8)  s_cp_b[tid]  = cp_b[tid];
    if (tid < 24) s_wdl_b[tid] = wdl_b[tid];

    const float2* ghp = (const float2*)g_h;

    auto stage = [&](int k) {
        int buf = k & 1;
        int c0  = k * CHUNK2;
        uint32_t hdst = sbase + K2_OFF_H + buf * K2_HBUF;
        uint32_t wdst = sbase + K2_OFF_W + buf * K2_WBUF;
        // h: 32 pair-rows x 64 c = 1024 cp16
        #pragma unroll
        for (int r = 0; r < 4; r++) {
            int u   = tid + r * K2T;
            int p   = u >> 5;            // pair row 0..31
            int c16 = u & 31;            // 16B unit within row
            cp_async16(hdst + (uint32_t)(p * 512 + c16 * 16),
                       ghp + ((size_t)(p0 + p) * HIDDEN + c0 + c16 * 2));
        }
        // wT chunk: contiguous 8KB = 512 cp16
        const char* wsrc = (const char*)(g_wT + (size_t)c0 * 32);
        #pragma unroll
        for (int r = 0; r < 2; r++) {
            int u = tid + r * K2T;
            cp_async16(wdst + (uint32_t)(u * 16), wsrc + u * 16);
        }
        CP_COMMIT();
    };

    stage(0);

    const int jq = tid & 15;     // j = 2jq, 2jq+1
    const int sg = tid >> 4;     // pairs 2sg, 2sg+1

    unsigned long long acc00 = 0ull, acc01 = 0ull, acc10 = 0ull, acc11 = 0ull;

    for (int k = 0; k < NCH2; k++) {
        CP_WAIT0();
        __syncthreads();
        if (k + 1 < NCH2) stage(k + 1);   // overlaps compute below

        int buf = k & 1;
        const unsigned long long* hb =
            (const unsigned long long*)(smem + K2_OFF_H + buf * K2_HBUF);
        const float* wb = (const float*)(smem + K2_OFF_W + buf * K2_WBUF);
        const unsigned long long* h0 = hb + (2 * sg) * CHUNK2;
        const unsigned long long* h1 = hb + (2 * sg + 1) * CHUNK2;

        #pragma unroll 8
        for (int c = 0; c < CHUNK2; c++) {
            unsigned long long hv0 = h0[c];
            unsigned long long hv1 = h1[c];
            unsigned long long W0 = packdup(wb[c * 32 + 2 * jq]);
            unsigned long long W1 = packdup(wb[c * 32 + 2 * jq + 1]);
            fma2(acc00, hv0, W0);
            fma2(acc01, hv0, W1);
            fma2(acc10, hv1, W0);
            fma2(acc11, hv1, W1);
        }
        __syncthreads();
    }

    // h2 = screlu(acc + b) into smem (reuse hbuf: 64*33*4 = 8448 B)
    float* s_h2 = (float*)(smem + K2_OFF_H);
    {
        unsigned long long accs[2][2] = {{acc00, acc01}, {acc10, acc11}};
        #pragma unroll
        for (int p = 0; p < 2; p++) {
            #pragma unroll
            for (int jj = 0; jj < 2; jj++) {
                int j = 2 * jq + jj;
                F2U u; u.u = accs[p][jj];
                s_h2[(4 * sg + 2 * p)     * 33 + j] = screlu1(u.f.x + s_fc2_b[j]);
                s_h2[(4 * sg + 2 * p + 1) * 33 + j] = screlu1(u.f.y + s_fc2_b[j]);
            }
        }
    }
    __syncthreads();

    // heads: one thread per sample
    if (tid < TS2) {
        int samp = s0 + tid;
        if (samp < B) {
            const int is64 = (*s_nz == 0);
            int pc = is64 ? (int)((const long long*)pcv)[samp]
                          : ((const int*)pcv)[samp];
            int bkt = (pc - 2) * 8 / 30;
            bkt = max(0, min(7, bkt));

            const float* h2 = &s_h2[tid * 33];
            float cp = s_cp_b[bkt];
            float w0 = s_wdl_b[bkt * 3 + 0];
            float w1 = s_wdl_b[bkt * 3 + 1];
            float w2 = s_wdl_b[bkt * 3 + 2];
            const float* cw  = &s_cp_w[bkt * 32];
            const float* ww0 = &s_wdl_w[(bkt * 3 + 0) * 32];
            const float* ww1 = &s_wdl_w[(bkt * 3 + 1) * 32];
            const float* ww2 = &s_wdl_w[(bkt * 3 + 2) * 32];
            #pragma unroll
            for (int j = 0; j < 32; j++) {
                float hh = h2[j];
                cp = fmaf(hh, cw[j],  cp);
                w0 = fmaf(hh, ww0[j], w0);
                w1 = fmaf(hh, ww1[j], w1);
                w2 = fmaf(hh, ww2[j], w2);
            }
            out[samp] = cp;
            out[B + samp * 3 + 0] = w0;
            out[B + samp * 3 + 1] = w1;
            out[B + samp * 3 + 2] = w2;
        }
    }
}

// ---------------------------------------------------------------------------
extern "C" void kernel_launch(void* const* d_in, const int* in_sizes, int n_in,
                              void* d_out, int out_size)
{
    const void*  x      = d_in[0];
    const void*  pc     = d_in[1];
    const float* emb    = (const float*)d_in[2];
    const float* bias1  = (const float*)d_in[3];
    const float* fc2_w  = (const float*)d_in[4];
    const float* fc2_b  = (const float*)d_in[5];
    const float* cp_w   = (const float*)d_in[6];
    const float* cp_b   = (const float*)d_in[7];
    const float* wdl_w  = (const float*)d_in[8];
    const float* wdl_b  = (const float*)d_in[9];

    int B = in_sizes[0] / 32;
    if (B > MAX_B) B = MAX_B;

    prep_kernel<<<NROWS + 64, 512>>>(emb, fc2_w);

    const int k1_smem = NROWS * CHUNK1 * 2 + 8192 + CHUNK1 * 4 + 16;
    cudaFuncSetAttribute(gather_kernel,
                         cudaFuncAttributeMaxDynamicSharedMemorySize, k1_smem);
    dim3 g1(NCHUNKS1, NGROUPS1);
    gather_kernel<<<g1, K1T, k1_smem>>>(x, bias1, B);

    cudaFuncSetAttribute(fc_kernel,
                         cudaFuncAttributeMaxDynamicSharedMemorySize, K2_SMEM);
    int g2 = (B + TS2 - 1) / TS2;
    fc_kernel<<<g2, K2T, K2_SMEM>>>(x, fc2_b, cp_w, cp_b, wdl_w, wdl_b,
                                    pc, (float*)d_out, B);
}

// round 12
// speedup vs baseline: 1.5417x; 1.0282x over previous
#include <cuda_runtime.h>
#include <cuda_fp16.h>
#include <cstdint>

// ---------------------------------------------------------------------------
// EvalNet: EmbeddingBag(sum,pad) -> screlu -> fc2(1024->32) -> screlu
//          -> bucketed cp/wdl heads.   (sm_100 SIMT)
// P : emb fp32->fp16 (769 blocks); w transpose g_wT[c*32+j] (64 blocks).
// K1: R6 gather with depth-2 HADD2 tree; h PAIR-INTERLEAVED fp32.
// K2: TRIPLE-buffered cp.async pipeline (wait_group 1, ONE barrier/chunk);
//     scalar-broadcast sample-pair FFMA2 inner loop; bucketed heads.
// ---------------------------------------------------------------------------

#define HIDDEN   1024
#define NROWS    769
#define MAX_B    16384
#define TILE     32

#define CHUNK1   128
#define NCHUNKS1 (HIDDEN / CHUNK1)   // 8
#define NGROUPS1 18                  // 8*18 = 144 blocks
#define K1T      512

#define K2T      256
#define TS2      64                  // samples per K2 block (grid 256)
#define CHUNK2   64
#define NCH2     (HIDDEN / CHUNK2)   // 16

__device__ float  g_h[(size_t)MAX_B * HIDDEN];   // pair-interleaved hidden
__device__ __half g_emb_h[NROWS * HIDDEN];       // fp16 table
__device__ float  g_wT[HIDDEN * 32];             // wT[c*32+j] = fc2_w[j][c]

__device__ __forceinline__ float screlu1(float v)
{
    float c = fminf(fmaxf(v, 0.0f), 1.0f);
    return c * c;
}

__device__ __forceinline__ void fma2(unsigned long long& acc,
                                     unsigned long long a,
                                     unsigned long long b)
{
    asm("fma.rn.f32x2 %0, %1, %2, %0;" : "+l"(acc) : "l"(a), "l"(b));
}

__device__ __forceinline__ void add2(unsigned long long& acc,
                                     unsigned long long v)
{
    asm("add.rn.f32x2 %0, %0, %1;" : "+l"(acc) : "l"(v));
}

__device__ __forceinline__ unsigned long long packdup(float w)
{
    unsigned long long r;
    asm("mov.b64 %0, {%1, %1};" : "=l"(r) : "f"(w));
    return r;
}

__device__ __forceinline__ uint32_t smem_u32(const void* p)
{
    uint32_t a;
    asm("{ .reg .u64 t; cvta.to.shared.u64 t, %1; cvt.u32.u64 %0, t; }"
        : "=r"(a) : "l"(p));
    return a;
}

__device__ __forceinline__ void cp_async16(uint32_t dst, const void* src)
{
    asm volatile("cp.async.ca.shared.global [%0], [%1], 16;"
                 :: "r"(dst), "l"(__cvta_generic_to_global(src)));
}

#define CP_COMMIT() asm volatile("cp.async.commit_group;" ::: "memory")
#define CP_WAIT0()  asm volatile("cp.async.wait_group 0;" ::: "memory")
#define CP_WAIT1()  asm volatile("cp.async.wait_group 1;" ::: "memory")

union F2U { float2 f; unsigned long long u; };

#define H2(u) (*(const __half2*)&(u))

// ---------------------------------------------------------------------------
// P: blocks 0..768: emb row -> fp16; blocks 769..832: wT build.
// ---------------------------------------------------------------------------
__global__ __launch_bounds__(512)
void prep_kernel(const float* __restrict__ emb,
                 const float* __restrict__ fc2_w)
{
    const int b = blockIdx.x, tid = threadIdx.x;
    if (b < NROWS) {
        const float2* src = (const float2*)(emb + b * HIDDEN);
        __half2* dst = (__half2*)(g_emb_h + b * HIDDEN);
        dst[tid] = __floats2half2_rn(src[tid].x, src[tid].y);
    } else {
        // i = j*1024 + c (coalesced reads); write g_wT[c*32 + j]
        int i = (b - NROWS) * 512 + tid;
        int j = i >> 10, c = i & 1023;
        g_wT[c * 32 + j] = fc2_w[i];
    }
}

// ---------------------------------------------------------------------------
// K1: gather + bias + screlu over a 128-col fp16 table slice.
// Depth-2 HADD2 tree (8 rows -> 2 fp16 partial sums) before f32x2 accumulate.
// ---------------------------------------------------------------------------
__global__ __launch_bounds__(K1T)
void gather_kernel(const void* __restrict__ xv,
                   const float* __restrict__ bias1,
                   int B)
{
    extern __shared__ char smem[];
    __half* s_tab  = (__half*)smem;                                  // NROWS*CHUNK1*2
    int*    s_idx  = (int*)(smem + NROWS * CHUNK1 * 2);              // 2*1024*4
    float*  s_bias = (float*)(smem + NROWS * CHUNK1 * 2 + 8192);     // CHUNK1*4
    int*    s_nz   = (int*)(smem + NROWS * CHUNK1 * 2 + 8192 + CHUNK1 * 4);

    const int tid   = threadIdx.x;
    const int cbase = blockIdx.x * CHUNK1;

    if (tid == 0) *s_nz = 0;
    __syncthreads();

    if (tid < 64) {
        if (((const unsigned int*)xv)[2 * tid + 1]) atomicOr(s_nz, 1);
    }

    {
        const uint4* src = (const uint4*)g_emb_h;       // row stride 128 uint4
        uint4*       dst = (uint4*)s_tab;               // row stride 16 uint4
        const int cb8 = cbase >> 3;
        for (int i = tid; i < NROWS * 16; i += K1T) {
            int row = i >> 4, u = i & 15;
            dst[i] = src[row * 128 + cb8 + u];
        }
    }
    if (tid < CHUNK1) s_bias[tid] = bias1[cbase + tid];
    __syncthreads();

    const int is64 = (*s_nz == 0);

    const int s   = tid >> 4;
    const int q   = tid & 15;
    const int odd = s & 1;

    const int spg     = (((B + NGROUPS1 - 1) / NGROUPS1) + TILE - 1) & ~(TILE - 1);
    const int s_begin = blockIdx.y * spg;
    const int s_end   = min(B, s_begin + spg);

    const int*       x32 = (const int*)xv;
    const long long* x64 = (const long long*)xv;
    float2*          ghp = (float2*)g_h;
    const uint4*     tab4 = (const uint4*)s_tab;

    int pre0 = NROWS - 1, pre1 = NROWS - 1;
    if (s_begin < s_end) {
        #pragma unroll
        for (int k = 0; k < 2; k++) {
            int j = tid + k * K1T;
            int samp = s_begin + (j >> 5);
            int v = NROWS - 1;
            if (samp < B) {
                int r = j & 31;
                v = is64 ? (int)x64[(size_t)samp * 32 + r]
                         : x32[samp * 32 + r];
            }
            if (k == 0) pre0 = v; else pre1 = v;
        }
    }

    int buf = 0;
    for (int t0 = s_begin; t0 < s_end; t0 += TILE) {
        s_idx[buf * 1024 + tid]       = pre0;
        s_idx[buf * 1024 + tid + K1T] = pre1;
        __syncthreads();

        int tn = t0 + TILE;
        if (tn < s_end) {
            #pragma unroll
            for (int k = 0; k < 2; k++) {
                int j = tid + k * K1T;
                int samp = tn + (j >> 5);
                int v = NROWS - 1;
                if (samp < B) {
                    int r = j & 31;
                    v = is64 ? (int)x64[(size_t)samp * 32 + r]
                             : x32[samp * 32 + r];
                }
                if (k == 0) pre0 = v; else pre1 = v;
            }
        }

        const int* idx = &s_idx[buf * 1024 + s * 32];

        unsigned long long a0 = 0ull, a1 = 0ull, a2 = 0ull, a3 = 0ull;
        #pragma unroll
        for (int r0 = 0; r0 < 32; r0 += 8) {
            int id[8];
            #pragma unroll
            for (int k = 0; k < 8; k++) id[k] = idx[r0 + k];
            uint4 v[8];
            #pragma unroll
            for (int k = 0; k < 8; k++) v[k] = tab4[id[k] * 16 + q];

            // depth-2 fp16 tree per component, then f32x2 accumulate
            #define TREE(COMP, ACC) do {                                         \
                __half2 d1 = __hadd2(__hadd2(H2(v[0].COMP), H2(v[1].COMP)),      \
                                     __hadd2(H2(v[2].COMP), H2(v[3].COMP)));     \
                __half2 d2 = __hadd2(__hadd2(H2(v[4].COMP), H2(v[5].COMP)),      \
                                     __hadd2(H2(v[6].COMP), H2(v[7].COMP)));     \
                F2U t1_, t2_;                                                    \
                t1_.f = __half22float2(d1);                                      \
                t2_.f = __half22float2(d2);                                      \
                add2(ACC, t1_.u);                                                \
                add2(ACC, t2_.u);                                                \
            } while (0)

            TREE(x, a0);
            TREE(y, a1);
            TREE(z, a2);
            TREE(w, a3);
            #undef TREE
        }

        int samp = t0 + s;

        float h[8];
        {
            F2U u0, u1, u2, u3;
            u0.u = a0; u1.u = a1; u2.u = a2; u3.u = a3;
            h[0] = u0.f.x; h[1] = u0.f.y; h[2] = u1.f.x; h[3] = u1.f.y;
            h[4] = u2.f.x; h[5] = u2.f.y; h[6] = u3.f.x; h[7] = u3.f.y;
            const float4 b0 = ((const float4*)s_bias)[2 * q];
            const float4 b1 = ((const float4*)s_bias)[2 * q + 1];
            h[0] = screlu1(h[0] + b0.x); h[1] = screlu1(h[1] + b0.y);
            h[2] = screlu1(h[2] + b0.z); h[3] = screlu1(h[3] + b0.w);
            h[4] = screlu1(h[4] + b1.x); h[5] = screlu1(h[5] + b1.y);
            h[6] = screlu1(h[6] + b1.z); h[7] = screlu1(h[7] + b1.w);
        }

        float p[8];
        #pragma unroll
        for (int k = 0; k < 8; k++)
            p[k] = __shfl_xor_sync(0xffffffffu, h[k], 16);

        if (samp < B) {
            size_t pr = (size_t)(samp >> 1);
            float2* base = ghp + pr * HIDDEN + cbase + 8 * q + odd * 4;
            if (!odd) {
                ((float4*)base)[0] = make_float4(h[0], p[0], h[1], p[1]);
                ((float4*)base)[1] = make_float4(h[2], p[2], h[3], p[3]);
            } else {
                ((float4*)base)[0] = make_float4(p[4], h[4], p[5], h[5]);
                ((float4*)base)[1] = make_float4(p[6], h[6], p[7], h[7]);
            }
        }
        buf ^= 1;
    }
}

// ---------------------------------------------------------------------------
// K2: fc2 via sample-pair FFMA2; TRIPLE-buffered cp.async (wait_group 1),
// one barrier per chunk. 256 threads, 64 samples/block.
// jq = tid&15 owns j {2jq, 2jq+1}; sg = tid>>4 owns pairs {2sg, 2sg+1}.
// ---------------------------------------------------------------------------
#define K2_OFF_H    0
#define K2_HBUF     16384              // 32 pairs * 64 ull * 8
#define K2_OFF_W    49152              // after 3 h buffers
#define K2_WBUF     8192               // 64 c * 32 j * 4
#define K2_OFF_CPW  73728              // after 3 w buffers
#define K2_OFF_WDLW 74752
#define K2_OFF_FB   77824
#define K2_OFF_CB   77952
#define K2_OFF_WB   77984
#define K2_OFF_NZ   78080
#define K2_SMEM     78096

__global__ __launch_bounds__(K2T)
void fc_kernel(const void* __restrict__ xv,
               const float* __restrict__ fc2_b,
               const float* __restrict__ cp_w,  const float* __restrict__ cp_b,
               const float* __restrict__ wdl_w, const float* __restrict__ wdl_b,
               const void* __restrict__ pcv, float* __restrict__ out, int B)
{
    extern __shared__ char smem[];
    const uint32_t sbase = smem_u32(smem);

    float* s_cp_w  = (float*)(smem + K2_OFF_CPW);
    float* s_wdl_w = (float*)(smem + K2_OFF_WDLW);
    float* s_fc2_b = (float*)(smem + K2_OFF_FB);
    float* s_cp_b  = (float*)(smem + K2_OFF_CB);
    float* s_wdl_b = (float*)(smem + K2_OFF_WB);
    int*   s_nz    = (int*)(smem + K2_OFF_NZ);

    const int tid = threadIdx.x;
    const int s0  = blockIdx.x * TS2;
    const int p0  = s0 >> 1;

    if (tid == 0) *s_nz = 0;
    __syncthreads();
    if (tid < 64) {
        if (((const unsigned int*)xv)[2 * tid + 1]) atomicOr(s_nz, 1);
    }
    for (int i = tid; i < 8 * 32; i += K2T)  s_cp_w[i]  = cp_w[i];
    for (int i = tid; i < 24 * 32; i += K2T) s_wdl_w[i] = wdl_w[i];
    if (tid < 32) s_fc2_b[tid] = fc2_b[tid];
    if (tid < 8)  s_cp_b[tid]  = cp_b[tid];
    if (tid < 24) s_wdl_b[tid] = wdl_b[tid];

    const float2* ghp = (const float2*)g_h;

    auto stage = [&](int k) {
        int buf = k % 3;
        int c0  = k * CHUNK2;
        uint32_t hdst = sbase + K2_OFF_H + buf * K2_HBUF;
        uint32_t wdst = sbase + K2_OFF_W + buf * K2_WBUF;
        // h: 32 pair-rows x 64 c = 1024 cp16
        #pragma unroll
        for (int r = 0; r < 4; r++) {
            int u   = tid + r * K2T;
            int p   = u >> 5;            // pair row 0..31
            int c16 = u & 31;            // 16B unit within row
            cp_async16(hdst + (uint32_t)(p * 512 + c16 * 16),
                       ghp + ((size_t)(p0 + p) * HIDDEN + c0 + c16 * 2));
        }
        // wT chunk: contiguous 8KB = 512 cp16
        const char* wsrc = (const char*)(g_wT + (size_t)c0 * 32);
        #pragma unroll
        for (int r = 0; r < 2; r++) {
            int u = tid + r * K2T;
            cp_async16(wdst + (uint32_t)(u * 16), wsrc + u * 16);
        }
        CP_COMMIT();
    };

    stage(0);
    stage(1);

    const int jq = tid & 15;     // j = 2jq, 2jq+1
    const int sg = tid >> 4;     // pairs 2sg, 2sg+1

    unsigned long long acc00 = 0ull, acc01 = 0ull, acc10 = 0ull, acc11 = 0ull;

    for (int k = 0; k < NCH2; k++) {
        // ensure stage(k) landed; stage(k+1) may still be in flight
        if (k == NCH2 - 1) { CP_WAIT0(); } else { CP_WAIT1(); }
        __syncthreads();                     // one barrier per chunk
        if (k + 2 < NCH2) stage(k + 2);      // overwrites buf read in chunk k-1

        int buf = k % 3;
        const unsigned long long* hb =
            (const unsigned long long*)(smem + K2_OFF_H + buf * K2_HBUF);
        const float* wb = (const float*)(smem + K2_OFF_W + buf * K2_WBUF);
        const unsigned long long* h0 = hb + (2 * sg) * CHUNK2;
        const unsigned long long* h1 = hb + (2 * sg + 1) * CHUNK2;

        #pragma unroll 8
        for (int c = 0; c < CHUNK2; c++) {
            unsigned long long hv0 = h0[c];
            unsigned long long hv1 = h1[c];
            unsigned long long W0 = packdup(wb[c * 32 + 2 * jq]);
            unsigned long long W1 = packdup(wb[c * 32 + 2 * jq + 1]);
            fma2(acc00, hv0, W0);
            fma2(acc01, hv0, W1);
            fma2(acc10, hv1, W0);
            fma2(acc11, hv1, W1);
        }
    }

    // h2 = screlu(acc + b) into smem (reuse hbuf: 64*33*4 = 8448 B)
    __syncthreads();                         // all reads of hbuf[0] done
    float* s_h2 = (float*)(smem + K2_OFF_H);
    {
        unsigned long long accs[2][2] = {{acc00, acc01}, {acc10, acc11}};
        #pragma unroll
        for (int p = 0; p < 2; p++) {
            #pragma unroll
            for (int jj = 0; jj < 2; jj++) {
                int j = 2 * jq + jj;
                F2U u; u.u = accs[p][jj];
                s_h2[(4 * sg + 2 * p)     * 33 + j] = screlu1(u.f.x + s_fc2_b[j]);
                s_h2[(4 * sg + 2 * p + 1) * 33 + j] = screlu1(u.f.y + s_fc2_b[j]);
            }
        }
    }
    __syncthreads();

    // heads: one thread per sample
    if (tid < TS2) {
        int samp = s0 + tid;
        if (samp < B) {
            const int is64 = (*s_nz == 0);
            int pc = is64 ? (int)((const long long*)pcv)[samp]
                          : ((const int*)pcv)[samp];
            int bkt = (pc - 2) * 8 / 30;
            bkt = max(0, min(7, bkt));

            const float* h2 = &s_h2[tid * 33];
            float cp = s_cp_b[bkt];
            float w0 = s_wdl_b[bkt * 3 + 0];
            float w1 = s_wdl_b[bkt * 3 + 1];
            float w2 = s_wdl_b[bkt * 3 + 2];
            const float* cw  = &s_cp_w[bkt * 32];
            const float* ww0 = &s_wdl_w[(bkt * 3 + 0) * 32];
            const float* ww1 = &s_wdl_w[(bkt * 3 + 1) * 32];
            const float* ww2 = &s_wdl_w[(bkt * 3 + 2) * 32];
            #pragma unroll
            for (int j = 0; j < 32; j++) {
                float hh = h2[j];
                cp = fmaf(hh, cw[j],  cp);
                w0 = fmaf(hh, ww0[j], w0);
                w1 = fmaf(hh, ww1[j], w1);
                w2 = fmaf(hh, ww2[j], w2);
            }
            out[samp] = cp;
            out[B + samp * 3 + 0] = w0;
            out[B + samp * 3 + 1] = w1;
            out[B + samp * 3 + 2] = w2;
        }
    }
}

// ---------------------------------------------------------------------------
extern "C" void kernel_launch(void* const* d_in, const int* in_sizes, int n_in,
                              void* d_out, int out_size)
{
    const void*  x      = d_in[0];
    const void*  pc     = d_in[1];
    const float* emb    = (const float*)d_in[2];
    const float* bias1  = (const float*)d_in[3];
    const float* fc2_w  = (const float*)d_in[4];
    const float* fc2_b  = (const float*)d_in[5];
    const float* cp_w   = (const float*)d_in[6];
    const float* cp_b   = (const float*)d_in[7];
    const float* wdl_w  = (const float*)d_in[8];
    const float* wdl_b  = (const float*)d_in[9];

    int B = in_sizes[0] / 32;
    if (B > MAX_B) B = MAX_B;

    prep_kernel<<<NROWS + 64, 512>>>(emb, fc2_w);

    const int k1_smem = NROWS * CHUNK1 * 2 + 8192 + CHUNK1 * 4 + 16;
    cudaFuncSetAttribute(gather_kernel,
                         cudaFuncAttributeMaxDynamicSharedMemorySize, k1_smem);
    dim3 g1(NCHUNKS1, NGROUPS1);
    gather_kernel<<<g1, K1T, k1_smem>>>(x, bias1, B);

    cudaFuncSetAttribute(fc_kernel,
                         cudaFuncAttributeMaxDynamicSharedMemorySize, K2_SMEM);
    int g2 = (B + TS2 - 1) / TS2;
    fc_kernel<<<g2, K2T, K2_SMEM>>>(x, fc2_b, cp_w, cp_b, wdl_w, wdl_b,
                                    pc, (float*)d_out, B);
}